// round 1
// baseline (speedup 1.0000x reference)
#include <cuda_runtime.h>
#include <math.h>

// ---- problem constants ----
#define Bq   4
#define Tt   10
#define CINq 8
#define Hh   96
#define Ww   96
#define HW   9216          // 96*96
#define HID  64
#define Lq   13
#define C3   192           // 3*hid
#define KW   832           // L*hid
#define FCH  32

// ---- scratch (device globals; no allocation allowed) ----
__device__ float g_i2h[(size_t)Bq * Tt * C3 * HW];      // 283 MB
__device__ float g_h[(size_t)Bq * HID * HW];            // 9.4 MB
__device__ float g_f[(size_t)Bq * FCH * HW];            // 4.7 MB
__device__ float g_flows[(size_t)Bq * 2 * Lq * HW];     // 3.8 MB
__device__ float g_warped[(size_t)Bq * KW * HW];        // 122.7 MB

// ---------------------------------------------------------------------------
// init: h = state
__global__ void k_init_h(const float* __restrict__ state) {
    int i = blockIdx.x * 256 + threadIdx.x;
    if (i < Bq * HID * HW) g_h[i] = state[i];
}
// tail: out_hlast = h
__global__ void k_hlast(float* __restrict__ dst) {
    int i = blockIdx.x * 256 + threadIdx.x;
    if (i < Bq * HID * HW) dst[i] = g_h[i];
}

// ---------------------------------------------------------------------------
// i2h: conv3x3 pad1, (40,8,96,96) -> (40,192,96,96). Runs once.
// block 128 thr (16x8), tile 16x16 px (each thread 2 px: y, y+8), co groups of 32.
__global__ __launch_bounds__(128)
void k_i2h(const float* __restrict__ x, const float* __restrict__ w,
           const float* __restrict__ bias) {
    __shared__ float s_in[CINq * 18 * 18];   // 2592
    __shared__ float s_w[32 * CINq * 9];     // 2304
    const int n  = blockIdx.z;
    const int y0 = blockIdx.y * 16, x0 = blockIdx.x * 16;
    const int tid = threadIdx.x;
    const int tx = tid & 15, ty = tid >> 4;  // ty 0..7

    const float* xin = x + (size_t)n * CINq * HW;
    for (int idx = tid; idx < CINq * 18 * 18; idx += 128) {
        int ci = idx / 324, r = (idx / 18) % 18, c = idx % 18;
        int gy = y0 - 1 + r, gx = x0 - 1 + c;
        float v = 0.f;
        if (gy >= 0 && gy < Hh && gx >= 0 && gx < Ww) v = xin[ci * HW + gy * Ww + gx];
        s_in[idx] = v;
    }

    for (int cob = 0; cob < C3; cob += 32) {
        __syncthreads();
        for (int idx = tid; idx < 32 * CINq * 9; idx += 128)
            s_w[idx] = w[cob * CINq * 9 + idx];
        __syncthreads();

        float acc0[32], acc1[32];
#pragma unroll
        for (int cc = 0; cc < 32; cc++) { float b = bias[cob + cc]; acc0[cc] = b; acc1[cc] = b; }

        for (int ci = 0; ci < CINq; ci++) {
#pragma unroll
            for (int ky = 0; ky < 3; ky++) {
                const float* r0 = &s_in[ci * 324 + (ty + ky) * 18 + tx];
                const float* r1 = &s_in[ci * 324 + (ty + 8 + ky) * 18 + tx];
#pragma unroll
                for (int kx = 0; kx < 3; kx++) {
                    float i0 = r0[kx], i1 = r1[kx];
                    const float* wp = &s_w[ci * 9 + ky * 3 + kx];
#pragma unroll
                    for (int cc = 0; cc < 32; cc++) {
                        float wv = wp[cc * 72];
                        acc0[cc] += i0 * wv;
                        acc1[cc] += i1 * wv;
                    }
                }
            }
        }
        float* outp = g_i2h + (size_t)n * C3 * HW + (size_t)cob * HW + (y0 + ty) * Ww + (x0 + tx);
#pragma unroll
        for (int cc = 0; cc < 32; cc++) {
            outp[(size_t)cc * HW] = acc0[cc];
            outp[(size_t)cc * HW + 8 * Ww] = acc1[cc];
        }
    }
}

// ---------------------------------------------------------------------------
// f = tanh(conv5x5(x_t, i2f) + conv5x5(h, h2f)) : (4,32,96,96)
// treat as one conv over 72 virtual input channels (9 chunks of 8).
__global__ __launch_bounds__(128)
void k_fconv(const float* __restrict__ xall, int t,
             const float* __restrict__ wi, const float* __restrict__ bi,
             const float* __restrict__ wh, const float* __restrict__ bh) {
    __shared__ float s_in[8 * 400];      // 20x20 x 8ch
    __shared__ float s_w[32 * 8 * 25];   // 6400
    const int b  = blockIdx.z;
    const int y0 = blockIdx.y * 16, x0 = blockIdx.x * 16;
    const int tid = threadIdx.x;
    const int tx = tid & 15, ty = tid >> 4;  // ty 0..7

    float acc0[32], acc1[32];
#pragma unroll
    for (int cc = 0; cc < 32; cc++) { float v = bi[cc] + bh[cc]; acc0[cc] = v; acc1[cc] = v; }

    for (int chunk = 0; chunk < 9; chunk++) {
        const float* src = (chunk == 0)
            ? xall + (size_t)(b * Tt + t) * CINq * HW
            : g_h + (size_t)b * HID * HW + (size_t)(chunk - 1) * 8 * HW;
        __syncthreads();
        for (int idx = tid; idx < 8 * 400; idx += 128) {
            int ci = idx / 400, r = (idx / 20) % 20, c = idx % 20;
            int gy = y0 - 2 + r, gx = x0 - 2 + c;
            float v = 0.f;
            if (gy >= 0 && gy < Hh && gx >= 0 && gx < Ww) v = src[ci * HW + gy * Ww + gx];
            s_in[idx] = v;
        }
        if (chunk == 0) {
            for (int idx = tid; idx < 32 * 200; idx += 128) s_w[idx] = wi[idx];
        } else {
            int cioff = (chunk - 1) * 8;
            for (int idx = tid; idx < 32 * 200; idx += 128) {
                int co = idx / 200, rem = idx % 200, ci = rem / 25, kk = rem % 25;
                s_w[idx] = wh[(co * 64 + cioff + ci) * 25 + kk];
            }
        }
        __syncthreads();
        for (int ci = 0; ci < 8; ci++) {
#pragma unroll
            for (int ky = 0; ky < 5; ky++) {
                const float* r0 = &s_in[ci * 400 + (ty + ky) * 20 + tx];
                const float* r1 = &s_in[ci * 400 + (ty + 8 + ky) * 20 + tx];
#pragma unroll
                for (int kx = 0; kx < 5; kx++) {
                    float i0 = r0[kx], i1 = r1[kx];
                    const float* wp = &s_w[ci * 25 + ky * 5 + kx];
#pragma unroll
                    for (int cc = 0; cc < 32; cc++) {
                        float wv = wp[cc * 200];
                        acc0[cc] += i0 * wv;
                        acc1[cc] += i1 * wv;
                    }
                }
            }
        }
    }
    float* outp = g_f + (size_t)b * FCH * HW + (y0 + ty) * Ww + (x0 + tx);
#pragma unroll
    for (int cc = 0; cc < 32; cc++) {
        outp[(size_t)cc * HW] = tanhf(acc0[cc]);
        outp[(size_t)cc * HW + 8 * Ww] = tanhf(acc1[cc]);
    }
}

// ---------------------------------------------------------------------------
// flows = conv5x5(f, flows_w) : (4,26,96,96). 4 chunks of 8 input channels.
__global__ __launch_bounds__(128)
void k_flows(const float* __restrict__ w, const float* __restrict__ bias) {
    __shared__ float s_in[8 * 400];
    __shared__ float s_w[26 * 8 * 25];   // 5200
    const int b  = blockIdx.z;
    const int y0 = blockIdx.y * 16, x0 = blockIdx.x * 16;
    const int tid = threadIdx.x;
    const int tx = tid & 15, ty = tid >> 4;

    float acc0[26], acc1[26];
#pragma unroll
    for (int cc = 0; cc < 26; cc++) { float v = bias[cc]; acc0[cc] = v; acc1[cc] = v; }

    for (int chunk = 0; chunk < 4; chunk++) {
        const float* src = g_f + (size_t)b * FCH * HW + (size_t)chunk * 8 * HW;
        __syncthreads();
        for (int idx = tid; idx < 8 * 400; idx += 128) {
            int ci = idx / 400, r = (idx / 20) % 20, c = idx % 20;
            int gy = y0 - 2 + r, gx = x0 - 2 + c;
            float v = 0.f;
            if (gy >= 0 && gy < Hh && gx >= 0 && gx < Ww) v = src[ci * HW + gy * Ww + gx];
            s_in[idx] = v;
        }
        int cioff = chunk * 8;
        for (int idx = tid; idx < 26 * 200; idx += 128) {
            int co = idx / 200, rem = idx % 200, ci = rem / 25, kk = rem % 25;
            s_w[idx] = w[(co * 32 + cioff + ci) * 25 + kk];
        }
        __syncthreads();
        for (int ci = 0; ci < 8; ci++) {
#pragma unroll
            for (int ky = 0; ky < 5; ky++) {
                const float* r0 = &s_in[ci * 400 + (ty + ky) * 20 + tx];
                const float* r1 = &s_in[ci * 400 + (ty + 8 + ky) * 20 + tx];
#pragma unroll
                for (int kx = 0; kx < 5; kx++) {
                    float i0 = r0[kx], i1 = r1[kx];
                    const float* wp = &s_w[ci * 25 + ky * 5 + kx];
#pragma unroll
                    for (int cc = 0; cc < 26; cc++) {
                        float wv = wp[cc * 200];
                        acc0[cc] += i0 * wv;
                        acc1[cc] += i1 * wv;
                    }
                }
            }
        }
    }
    float* outp = g_flows + (size_t)b * 2 * Lq * HW + (y0 + ty) * Ww + (x0 + tx);
#pragma unroll
    for (int cc = 0; cc < 26; cc++) {
        outp[(size_t)cc * HW] = acc0[cc];
        outp[(size_t)cc * HW + 8 * Ww] = acc1[cc];
    }
}

// ---------------------------------------------------------------------------
// grid-sample gather: warped[b, l*64+c, p] = bilinear(h[b,c], x-fx-0.5, y-fy-0.5)
// one thread per (b,l,pixel), loops over 64 channels (indices/weights reused).
__global__ void k_gather() {
    int gid = blockIdx.x * 256 + threadIdx.x;
    if (gid >= Bq * Lq * HW) return;
    int p = gid % HW;
    int l = (gid / HW) % Lq;
    int b = gid / (HW * Lq);
    int x = p % Ww, y = p / Ww;

    float fx = g_flows[((size_t)b * 2 * Lq + 2 * l) * HW + p];
    float fy = g_flows[((size_t)b * 2 * Lq + 2 * l + 1) * HW + p];
    float ix = (float)x - fx - 0.5f;
    float iy = (float)y - fy - 0.5f;
    float ix0f = floorf(ix), iy0f = floorf(iy);
    float wx1 = ix - ix0f, wy1 = iy - iy0f;
    float wx0 = 1.f - wx1, wy0 = 1.f - wy1;
    int ix0 = (int)ix0f, iy0 = (int)iy0f;
    int ix1 = ix0 + 1,   iy1 = iy0 + 1;

    bool vx0 = (ix0 >= 0 && ix0 < Ww), vx1 = (ix1 >= 0 && ix1 < Ww);
    bool vy0 = (iy0 >= 0 && iy0 < Hh), vy1 = (iy1 >= 0 && iy1 < Hh);
    float w00 = (vy0 && vx0) ? wy0 * wx0 : 0.f;
    float w01 = (vy0 && vx1) ? wy0 * wx1 : 0.f;
    float w10 = (vy1 && vx0) ? wy1 * wx0 : 0.f;
    float w11 = (vy1 && vx1) ? wy1 * wx1 : 0.f;
    int xc0 = min(max(ix0, 0), Ww - 1), xc1 = min(max(ix1, 0), Ww - 1);
    int yc0 = min(max(iy0, 0), Hh - 1), yc1 = min(max(iy1, 0), Hh - 1);
    int o00 = yc0 * Ww + xc0, o01 = yc0 * Ww + xc1;
    int o10 = yc1 * Ww + xc0, o11 = yc1 * Ww + xc1;

    const float* hb = g_h + (size_t)b * HID * HW;
    float* wp = g_warped + ((size_t)b * KW + (size_t)l * HID) * HW + p;
#pragma unroll 4
    for (int c = 0; c < HID; c++) {
        const float* hc = hb + (size_t)c * HW;
        float v = w00 * hc[o00] + w01 * hc[o01] + w10 * hc[o10] + w11 * hc[o11];
        wp[(size_t)c * HW] = v;
    }
}

// ---------------------------------------------------------------------------
// h2h GEMM + fused GRU gates.
// C[p, o] = sum_k warped[b, k, p] * wrap_w[o, k];  tile P=64, O=192, Kc=16.
// 256 thr (tx=pixel lane 0..15, ty=channel lane 0..15); acc[4 px][12 o].
__global__ __launch_bounds__(256)
void k_gemm_gates(const float* __restrict__ wrap_w, const float* __restrict__ wrap_b,
                  float* __restrict__ out, int t) {
    __shared__ float a_s[16 * 64];
    __shared__ float b_s[16 * 192];
    const int b  = blockIdx.y;
    const int p0 = blockIdx.x * 64;
    const int tid = threadIdx.x;
    const int tx = tid & 15, ty = tid >> 4;

    float acc[4][12];
#pragma unroll
    for (int i = 0; i < 4; i++)
#pragma unroll
        for (int j = 0; j < 12; j++) acc[i][j] = 0.f;

    const float* A = g_warped + (size_t)b * KW * HW;

    for (int k0 = 0; k0 < KW; k0 += 16) {
        __syncthreads();
        {   // A tile: 16 k-rows x 64 pixels (float4, coalesced)
            int idx = tid * 4;
            int kk = idx >> 6, p = idx & 63;
            float4 v = *(const float4*)(A + (size_t)(k0 + kk) * HW + p0 + p);
            *(float4*)(a_s + idx) = v;
        }
        for (int idx = tid; idx < 3072; idx += 256) {  // B tile: transpose to [kk][o]
            int kk = idx & 15, o = idx >> 4;
            b_s[kk * 192 + o] = wrap_w[o * KW + k0 + kk];
        }
        __syncthreads();
#pragma unroll
        for (int kk = 0; kk < 16; kk++) {
            float av[4], bv[12];
#pragma unroll
            for (int i = 0; i < 4; i++) av[i] = a_s[kk * 64 + tx + 16 * i];
#pragma unroll
            for (int j = 0; j < 12; j++) bv[j] = b_s[kk * 192 + ty + 16 * j];
#pragma unroll
            for (int i = 0; i < 4; i++)
#pragma unroll
                for (int j = 0; j < 12; j++) acc[i][j] += av[i] * bv[j];
        }
    }

    // epilogue: gates + state update
    const float* i2hp = g_i2h + (size_t)(b * Tt + t) * C3 * HW;
#pragma unroll
    for (int i = 0; i < 4; i++) {
        int p = p0 + tx + 16 * i;
#pragma unroll
        for (int j = 0; j < 4; j++) {
            int c = ty + 16 * j;
            float rh = acc[i][j]     + __ldg(&wrap_b[c]);
            float uh = acc[i][j + 4] + __ldg(&wrap_b[c + 64]);
            float nh = acc[i][j + 8] + __ldg(&wrap_b[c + 128]);
            float r = 1.f / (1.f + expf(-(i2hp[(size_t)c * HW + p] + rh)));
            float u = 1.f / (1.f + expf(-(i2hp[(size_t)(c + 64) * HW + p] + uh)));
            float n = 1.f / (1.f + expf(-(i2hp[(size_t)(c + 128) * HW + p] + r * nh)));
            size_t hidx = ((size_t)b * HID + c) * HW + p;
            float hp = g_h[hidx];
            float hn = (1.f - u) * n + u * hp;
            g_h[hidx] = hn;
            out[((size_t)(b * Tt + t) * HID + c) * HW + p] = hn;
        }
    }
}

// ---------------------------------------------------------------------------
extern "C" void kernel_launch(void* const* d_in, const int* in_sizes, int n_in,
                              void* d_out, int out_size) {
    const float* inputs  = (const float*)d_in[0];
    const float* state   = (const float*)d_in[1];
    const float* i2h_w   = (const float*)d_in[2];
    const float* i2h_b   = (const float*)d_in[3];
    const float* i2f_w   = (const float*)d_in[4];
    const float* i2f_b   = (const float*)d_in[5];
    const float* h2f_w   = (const float*)d_in[6];
    const float* h2f_b   = (const float*)d_in[7];
    const float* flows_w = (const float*)d_in[8];
    const float* flows_b = (const float*)d_in[9];
    const float* wrap_w  = (const float*)d_in[10];
    const float* wrap_b  = (const float*)d_in[11];
    float* out = (float*)d_out;

    const int nh = Bq * HID * HW;
    k_init_h<<<(nh + 255) / 256, 256>>>(state);
    k_i2h<<<dim3(6, 6, Bq * Tt), 128>>>(inputs, i2h_w, i2h_b);

    for (int t = 0; t < Tt; t++) {
        k_fconv<<<dim3(6, 6, Bq), 128>>>(inputs, t, i2f_w, i2f_b, h2f_w, h2f_b);
        k_flows<<<dim3(6, 6, Bq), 128>>>(flows_w, flows_b);
        k_gather<<<(Bq * Lq * HW + 255) / 256, 256>>>();
        k_gemm_gates<<<dim3(HW / 64, Bq), 256>>>(wrap_w, wrap_b, out, t);
    }

    // h_last appended after outputs (only if the harness allocated room for it)
    long long outputs_elems = (long long)Bq * Tt * HID * HW;
    if ((long long)out_size >= outputs_elems + nh) {
        k_hlast<<<(nh + 255) / 256, 256>>>(out + outputs_elems);
    }
}

// round 3
// speedup vs baseline: 1.4215x; 1.4215x over previous
#include <cuda_runtime.h>
#include <math.h>
#include <stdint.h>

// ---- problem constants ----
#define Bq   4
#define Tt   10
#define CINq 8
#define Hh   96
#define Ww   96
#define HW   9216          // 96*96
#define HID  64
#define Lq   13
#define C3   192           // 3*hid
#define KW   832           // L*hid
#define FCH  32

// ---- scratch (device globals; no allocation allowed) ----
__device__ float g_i2h[(size_t)Bq * Tt * C3 * HW];      // 283 MB
__device__ float g_h[(size_t)Bq * HID * HW];            // 9.4 MB
__device__ float g_f[(size_t)Bq * FCH * HW];            // 4.7 MB
__device__ float g_flows[(size_t)Bq * 2 * Lq * HW];     // 3.8 MB
__device__ float g_warpedT[(size_t)Bq * HW * KW];       // 122.7 MB  [b][p][k]

// ---------------------------------------------------------------------------
__global__ void k_init_h(const float* __restrict__ state) {
    int i = blockIdx.x * 256 + threadIdx.x;
    if (i < Bq * HID * HW) g_h[i] = state[i];
}
__global__ void k_hlast(float* __restrict__ dst) {
    int i = blockIdx.x * 256 + threadIdx.x;
    if (i < Bq * HID * HW) dst[i] = g_h[i];
}

// ---------------------------------------------------------------------------
// i2h: conv3x3 pad1, (40,8,96,96) -> (40,192,96,96). Runs once.
// grid (6,6,120): z = n + 40*half, half picks 64 of the 192 output channels.
__global__ __launch_bounds__(128)
void k_i2h(const float* __restrict__ x, const float* __restrict__ w,
           const float* __restrict__ bias) {
    __shared__ float s_in[CINq * 18 * 18];
    __shared__ float s_w[32 * CINq * 9];
    const int n    = blockIdx.z % 40;
    const int half = blockIdx.z / 40;
    const int y0 = blockIdx.y * 16, x0 = blockIdx.x * 16;
    const int tid = threadIdx.x;
    const int tx = tid & 15, ty = tid >> 4;

    const float* xin = x + (size_t)n * CINq * HW;
    for (int idx = tid; idx < CINq * 18 * 18; idx += 128) {
        int ci = idx / 324, r = (idx / 18) % 18, c = idx % 18;
        int gy = y0 - 1 + r, gx = x0 - 1 + c;
        float v = 0.f;
        if (gy >= 0 && gy < Hh && gx >= 0 && gx < Ww) v = xin[ci * HW + gy * Ww + gx];
        s_in[idx] = v;
    }
    for (int cob = half * 64; cob < half * 64 + 64; cob += 32) {
        __syncthreads();
        for (int idx = tid; idx < 32 * CINq * 9; idx += 128)
            s_w[idx] = w[cob * CINq * 9 + idx];
        __syncthreads();
        float acc0[32], acc1[32];
#pragma unroll
        for (int cc = 0; cc < 32; cc++) { float b = bias[cob + cc]; acc0[cc] = b; acc1[cc] = b; }
        for (int ci = 0; ci < CINq; ci++) {
#pragma unroll
            for (int ky = 0; ky < 3; ky++) {
                const float* r0 = &s_in[ci * 324 + (ty + ky) * 18 + tx];
                const float* r1 = &s_in[ci * 324 + (ty + 8 + ky) * 18 + tx];
#pragma unroll
                for (int kx = 0; kx < 3; kx++) {
                    float i0 = r0[kx], i1 = r1[kx];
                    const float* wp = &s_w[ci * 9 + ky * 3 + kx];
#pragma unroll
                    for (int cc = 0; cc < 32; cc++) {
                        float wv = wp[cc * 72];
                        acc0[cc] += i0 * wv;
                        acc1[cc] += i1 * wv;
                    }
                }
            }
        }
        float* outp = g_i2h + (size_t)n * C3 * HW + (size_t)cob * HW + (y0 + ty) * Ww + (x0 + tx);
#pragma unroll
        for (int cc = 0; cc < 32; cc++) {
            outp[(size_t)cc * HW] = acc0[cc];
            outp[(size_t)cc * HW + 8 * Ww] = acc1[cc];
        }
    }
}

// ---------------------------------------------------------------------------
// f = tanh(conv5x5(x_t, i2f) + conv5x5(h, h2f)) : (4,32,96,96)
// grid (6,6,8): z = b + 4*grp, grp picks 16 of 32 output channels.
__global__ __launch_bounds__(128)
void k_fconv(const float* __restrict__ xall, int t,
             const float* __restrict__ wi, const float* __restrict__ bi,
             const float* __restrict__ wh, const float* __restrict__ bh) {
    __shared__ float s_in[8 * 400];
    __shared__ float s_w[16 * 8 * 25];
    const int b   = blockIdx.z & 3;
    const int grp = blockIdx.z >> 2;       // 0/1
    const int co0 = grp * 16;
    const int y0 = blockIdx.y * 16, x0 = blockIdx.x * 16;
    const int tid = threadIdx.x;
    const int tx = tid & 15, ty = tid >> 4;

    float acc0[16], acc1[16];
#pragma unroll
    for (int cc = 0; cc < 16; cc++) { float v = bi[co0 + cc] + bh[co0 + cc]; acc0[cc] = v; acc1[cc] = v; }

    for (int chunk = 0; chunk < 9; chunk++) {
        const float* src = (chunk == 0)
            ? xall + (size_t)(b * Tt + t) * CINq * HW
            : g_h + (size_t)b * HID * HW + (size_t)(chunk - 1) * 8 * HW;
        __syncthreads();
        for (int idx = tid; idx < 8 * 400; idx += 128) {
            int ci = idx / 400, r = (idx / 20) % 20, c = idx % 20;
            int gy = y0 - 2 + r, gx = x0 - 2 + c;
            float v = 0.f;
            if (gy >= 0 && gy < Hh && gx >= 0 && gx < Ww) v = src[ci * HW + gy * Ww + gx];
            s_in[idx] = v;
        }
        if (chunk == 0) {
            for (int idx = tid; idx < 16 * 200; idx += 128) s_w[idx] = wi[co0 * 200 + idx];
        } else {
            int cioff = (chunk - 1) * 8;
            for (int idx = tid; idx < 16 * 200; idx += 128) {
                int co = idx / 200, rem = idx % 200, ci = rem / 25, kk = rem % 25;
                s_w[idx] = wh[((co0 + co) * 64 + cioff + ci) * 25 + kk];
            }
        }
        __syncthreads();
        for (int ci = 0; ci < 8; ci++) {
#pragma unroll
            for (int ky = 0; ky < 5; ky++) {
                const float* r0 = &s_in[ci * 400 + (ty + ky) * 20 + tx];
                const float* r1 = &s_in[ci * 400 + (ty + 8 + ky) * 20 + tx];
#pragma unroll
                for (int kx = 0; kx < 5; kx++) {
                    float i0 = r0[kx], i1 = r1[kx];
                    const float* wp = &s_w[ci * 25 + ky * 5 + kx];
#pragma unroll
                    for (int cc = 0; cc < 16; cc++) {
                        float wv = wp[cc * 200];
                        acc0[cc] += i0 * wv;
                        acc1[cc] += i1 * wv;
                    }
                }
            }
        }
    }
    float* outp = g_f + (size_t)b * FCH * HW + (size_t)co0 * HW + (y0 + ty) * Ww + (x0 + tx);
#pragma unroll
    for (int cc = 0; cc < 16; cc++) {
        outp[(size_t)cc * HW] = tanhf(acc0[cc]);
        outp[(size_t)cc * HW + 8 * Ww] = tanhf(acc1[cc]);
    }
}

// ---------------------------------------------------------------------------
// flows = conv5x5(f, flows_w) : (4,26,96,96). grid (6,6,8): 2 groups of 13 co.
__global__ __launch_bounds__(128)
void k_flows(const float* __restrict__ w, const float* __restrict__ bias) {
    __shared__ float s_in[8 * 400];
    __shared__ float s_w[13 * 8 * 25];
    const int b   = blockIdx.z & 3;
    const int grp = blockIdx.z >> 2;
    const int co0 = grp * 13;
    const int y0 = blockIdx.y * 16, x0 = blockIdx.x * 16;
    const int tid = threadIdx.x;
    const int tx = tid & 15, ty = tid >> 4;

    float acc0[13], acc1[13];
#pragma unroll
    for (int cc = 0; cc < 13; cc++) { float v = bias[co0 + cc]; acc0[cc] = v; acc1[cc] = v; }

    for (int chunk = 0; chunk < 4; chunk++) {
        const float* src = g_f + (size_t)b * FCH * HW + (size_t)chunk * 8 * HW;
        __syncthreads();
        for (int idx = tid; idx < 8 * 400; idx += 128) {
            int ci = idx / 400, r = (idx / 20) % 20, c = idx % 20;
            int gy = y0 - 2 + r, gx = x0 - 2 + c;
            float v = 0.f;
            if (gy >= 0 && gy < Hh && gx >= 0 && gx < Ww) v = src[ci * HW + gy * Ww + gx];
            s_in[idx] = v;
        }
        int cioff = chunk * 8;
        for (int idx = tid; idx < 13 * 200; idx += 128) {
            int co = idx / 200, rem = idx % 200, ci = rem / 25, kk = rem % 25;
            s_w[idx] = w[((co0 + co) * 32 + cioff + ci) * 25 + kk];
        }
        __syncthreads();
        for (int ci = 0; ci < 8; ci++) {
#pragma unroll
            for (int ky = 0; ky < 5; ky++) {
                const float* r0 = &s_in[ci * 400 + (ty + ky) * 20 + tx];
                const float* r1 = &s_in[ci * 400 + (ty + 8 + ky) * 20 + tx];
#pragma unroll
                for (int kx = 0; kx < 5; kx++) {
                    float i0 = r0[kx], i1 = r1[kx];
                    const float* wp = &s_w[ci * 25 + ky * 5 + kx];
#pragma unroll
                    for (int cc = 0; cc < 13; cc++) {
                        float wv = wp[cc * 200];
                        acc0[cc] += i0 * wv;
                        acc1[cc] += i1 * wv;
                    }
                }
            }
        }
    }
    float* outp = g_flows + (size_t)b * 2 * Lq * HW + (size_t)co0 * HW + (y0 + ty) * Ww + (x0 + tx);
#pragma unroll
    for (int cc = 0; cc < 13; cc++) {
        outp[(size_t)cc * HW] = acc0[cc];
        outp[(size_t)cc * HW + 8 * Ww] = acc1[cc];
    }
}

// ---------------------------------------------------------------------------
// gather -> warpedT[b][p][k=l*64+c] (K-major rows for the mma GEMM)
__global__ void k_gather() {
    int gid = blockIdx.x * 256 + threadIdx.x;
    if (gid >= Bq * Lq * HW) return;
    int p = gid % HW;
    int l = (gid / HW) % Lq;
    int b = gid / (HW * Lq);
    int x = p % Ww, y = p / Ww;

    float fx = g_flows[((size_t)b * 2 * Lq + 2 * l) * HW + p];
    float fy = g_flows[((size_t)b * 2 * Lq + 2 * l + 1) * HW + p];
    float ix = (float)x - fx - 0.5f;
    float iy = (float)y - fy - 0.5f;
    float ix0f = floorf(ix), iy0f = floorf(iy);
    float wx1 = ix - ix0f, wy1 = iy - iy0f;
    float wx0 = 1.f - wx1, wy0 = 1.f - wy1;
    int ix0 = (int)ix0f, iy0 = (int)iy0f;
    int ix1 = ix0 + 1,   iy1 = iy0 + 1;

    bool vx0 = (ix0 >= 0 && ix0 < Ww), vx1 = (ix1 >= 0 && ix1 < Ww);
    bool vy0 = (iy0 >= 0 && iy0 < Hh), vy1 = (iy1 >= 0 && iy1 < Hh);
    float w00 = (vy0 && vx0) ? wy0 * wx0 : 0.f;
    float w01 = (vy0 && vx1) ? wy0 * wx1 : 0.f;
    float w10 = (vy1 && vx0) ? wy1 * wx0 : 0.f;
    float w11 = (vy1 && vx1) ? wy1 * wx1 : 0.f;
    int xc0 = min(max(ix0, 0), Ww - 1), xc1 = min(max(ix1, 0), Ww - 1);
    int yc0 = min(max(iy0, 0), Hh - 1), yc1 = min(max(iy1, 0), Hh - 1);
    int o00 = yc0 * Ww + xc0, o01 = yc0 * Ww + xc1;
    int o10 = yc1 * Ww + xc0, o11 = yc1 * Ww + xc1;

    const float* hb = g_h + (size_t)b * HID * HW;
    float* wp = g_warpedT + ((size_t)b * HW + p) * KW + l * HID;
#pragma unroll 4
    for (int c = 0; c < HID; c += 4) {
        float4 v;
        const float* h0 = hb + (size_t)c * HW;
        v.x = w00 * h0[o00] + w01 * h0[o01] + w10 * h0[o10] + w11 * h0[o11];
        const float* h1 = h0 + HW;
        v.y = w00 * h1[o00] + w01 * h1[o01] + w10 * h1[o10] + w11 * h1[o11];
        const float* h2 = h1 + HW;
        v.z = w00 * h2[o00] + w01 * h2[o01] + w10 * h2[o10] + w11 * h2[o11];
        const float* h3 = h2 + HW;
        v.w = w00 * h3[o00] + w01 * h3[o01] + w10 * h3[o10] + w11 * h3[o11];
        *(float4*)(wp + c) = v;
    }
}

// ---------------------------------------------------------------------------
// h2h GEMM via mma.sync m16n8k8 tf32 (3xTF32 hi/lo for fp32 accuracy)
// + fused GRU gates. CTA: 128 px x 192 gates, K=832 in 26 chunks of 32.
// 8 warps in a 2(M) x 4(N) grid; warp tile 64x48 (4 m-tiles x 6 n-tiles).
#define AS 36          // A/B smem row stride (words) -> conflict-free frags
#define CS 197         // C smem row stride (words)
#define GW_AHI 0
#define GW_ALO 4608    // 128*36
#define GW_BHI 9216
#define GW_BLO 16128   // +192*36
#define G_SMEM_BYTES (128 * CS * 4 > 23040 * 4 ? 128 * CS * 4 : 23040 * 4)

__device__ __forceinline__ uint32_t tf32r(float x) {
    uint32_t r;
    asm("cvt.rna.tf32.f32 %0, %1;" : "=r"(r) : "f"(x));
    return r;
}
__device__ __forceinline__ void mma8(float d[4], const uint32_t a[4],
                                     uint32_t b0, uint32_t b1) {
    asm volatile(
        "mma.sync.aligned.m16n8k8.row.col.f32.tf32.tf32.f32 "
        "{%0,%1,%2,%3}, {%4,%5,%6,%7}, {%8,%9}, {%0,%1,%2,%3};"
        : "+f"(d[0]), "+f"(d[1]), "+f"(d[2]), "+f"(d[3])
        : "r"(a[0]), "r"(a[1]), "r"(a[2]), "r"(a[3]), "r"(b0), "r"(b1));
}

__global__ __launch_bounds__(256, 1)
void k_gemm_mma(const float* __restrict__ wrap_w, const float* __restrict__ wrap_b,
                float* __restrict__ out, int t) {
    extern __shared__ __align__(16) float sm[];
    uint32_t* Ah = (uint32_t*)(sm + GW_AHI);
    uint32_t* Al = (uint32_t*)(sm + GW_ALO);
    uint32_t* Bh = (uint32_t*)(sm + GW_BHI);
    uint32_t* Bl = (uint32_t*)(sm + GW_BLO);

    const int tid = threadIdx.x;
    const int wid = tid >> 5, lane = tid & 31;
    const int g = lane >> 2, tg = lane & 3;
    const int b  = blockIdx.y;
    const int p0 = blockIdx.x * 128;
    const int wm = (wid >> 2) * 64;     // warp M offset (pixels)
    const int wn = (wid & 3) * 48;      // warp N offset (gates)

    float acc[4][6][4];
#pragma unroll
    for (int mt = 0; mt < 4; mt++)
#pragma unroll
        for (int nt = 0; nt < 6; nt++)
#pragma unroll
            for (int q = 0; q < 4; q++) acc[mt][nt][q] = 0.f;

    const float* A = g_warpedT + ((size_t)b * HW + p0) * KW;

    for (int c = 0; c < 26; c++) {
        const int k0 = c * 32;
        __syncthreads();
        // stage A: 128 rows x 32 k (1024 float4)
#pragma unroll
        for (int i = 0; i < 4; i++) {
            int idx = tid + 256 * i;
            int row = idx >> 3, cc = idx & 7;
            float4 v = *(const float4*)(A + (size_t)row * KW + k0 + cc * 4);
            uint32_t hx = tf32r(v.x), hy = tf32r(v.y), hz = tf32r(v.z), hw = tf32r(v.w);
            int off = row * AS + cc * 4;
            *(uint4*)(Ah + off) = make_uint4(hx, hy, hz, hw);
            *(uint4*)(Al + off) = make_uint4(
                tf32r(v.x - __uint_as_float(hx)), tf32r(v.y - __uint_as_float(hy)),
                tf32r(v.z - __uint_as_float(hz)), tf32r(v.w - __uint_as_float(hw)));
        }
        // stage B: 192 rows x 32 k (1536 float4)
#pragma unroll
        for (int i = 0; i < 6; i++) {
            int idx = tid + 256 * i;
            int row = idx >> 3, cc = idx & 7;
            float4 v = *(const float4*)(wrap_w + (size_t)row * KW + k0 + cc * 4);
            uint32_t hx = tf32r(v.x), hy = tf32r(v.y), hz = tf32r(v.z), hw = tf32r(v.w);
            int off = row * AS + cc * 4;
            *(uint4*)(Bh + off) = make_uint4(hx, hy, hz, hw);
            *(uint4*)(Bl + off) = make_uint4(
                tf32r(v.x - __uint_as_float(hx)), tf32r(v.y - __uint_as_float(hy)),
                tf32r(v.z - __uint_as_float(hz)), tf32r(v.w - __uint_as_float(hw)));
        }
        __syncthreads();

#pragma unroll
        for (int ks = 0; ks < 4; ks++) {
            const int kk = ks * 8;
            uint32_t ahi[4][4], alo[4][4];
#pragma unroll
            for (int mt = 0; mt < 4; mt++) {
                int base = (wm + mt * 16 + g) * AS + kk + tg;
                ahi[mt][0] = Ah[base];            ahi[mt][2] = Ah[base + 4];
                ahi[mt][1] = Ah[base + 8 * AS];   ahi[mt][3] = Ah[base + 8 * AS + 4];
                alo[mt][0] = Al[base];            alo[mt][2] = Al[base + 4];
                alo[mt][1] = Al[base + 8 * AS];   alo[mt][3] = Al[base + 8 * AS + 4];
            }
#pragma unroll
            for (int nt = 0; nt < 6; nt++) {
                int rb = (wn + nt * 8 + g) * AS + kk + tg;
                uint32_t bh0 = Bh[rb], bh1 = Bh[rb + 4];
                uint32_t bl0 = Bl[rb], bl1 = Bl[rb + 4];
#pragma unroll
                for (int mt = 0; mt < 4; mt++) {
                    mma8(acc[mt][nt], ahi[mt], bh0, bh1);
                    mma8(acc[mt][nt], ahi[mt], bl0, bl1);
                    mma8(acc[mt][nt], alo[mt], bh0, bh1);
                }
            }
        }
    }

    // ---- write fragments to SMEM C tile, then fused gates ----
    __syncthreads();
    float* C = sm;
#pragma unroll
    for (int mt = 0; mt < 4; mt++) {
#pragma unroll
        for (int nt = 0; nt < 6; nt++) {
            int row = wm + mt * 16 + g;
            int col = wn + nt * 8 + tg * 2;
            C[row * CS + col]           = acc[mt][nt][0];
            C[row * CS + col + 1]       = acc[mt][nt][1];
            C[(row + 8) * CS + col]     = acc[mt][nt][2];
            C[(row + 8) * CS + col + 1] = acc[mt][nt][3];
        }
    }
    __syncthreads();

    const float* i2hp = g_i2h + (size_t)(b * Tt + t) * C3 * HW;
#pragma unroll 4
    for (int idx = tid; idx < 128 * 64; idx += 256) {
        int pl = idx & 127, cc = idx >> 7;
        int p = p0 + pl;
        float rh = C[pl * CS + cc]       + __ldg(&wrap_b[cc]);
        float uh = C[pl * CS + cc + 64]  + __ldg(&wrap_b[cc + 64]);
        float nh = C[pl * CS + cc + 128] + __ldg(&wrap_b[cc + 128]);
        float r = 1.f / (1.f + expf(-(i2hp[(size_t)cc * HW + p] + rh)));
        float u = 1.f / (1.f + expf(-(i2hp[(size_t)(cc + 64) * HW + p] + uh)));
        float n = 1.f / (1.f + expf(-(i2hp[(size_t)(cc + 128) * HW + p] + r * nh)));
        size_t hidx = ((size_t)b * HID + cc) * HW + p;
        float hp = g_h[hidx];
        float hn = (1.f - u) * n + u * hp;
        g_h[hidx] = hn;
        out[((size_t)(b * Tt + t) * HID + cc) * HW + p] = hn;
    }
}

// ---------------------------------------------------------------------------
extern "C" void kernel_launch(void* const* d_in, const int* in_sizes, int n_in,
                              void* d_out, int out_size) {
    const float* inputs  = (const float*)d_in[0];
    const float* state   = (const float*)d_in[1];
    const float* i2h_w   = (const float*)d_in[2];
    const float* i2h_b   = (const float*)d_in[3];
    const float* i2f_w   = (const float*)d_in[4];
    const float* i2f_b   = (const float*)d_in[5];
    const float* h2f_w   = (const float*)d_in[6];
    const float* h2f_b   = (const float*)d_in[7];
    const float* flows_w = (const float*)d_in[8];
    const float* flows_b = (const float*)d_in[9];
    const float* wrap_w  = (const float*)d_in[10];
    const float* wrap_b  = (const float*)d_in[11];
    float* out = (float*)d_out;

    cudaFuncSetAttribute(k_gemm_mma, cudaFuncAttributeMaxDynamicSharedMemorySize,
                         G_SMEM_BYTES);

    const int nh = Bq * HID * HW;
    k_init_h<<<(nh + 255) / 256, 256>>>(state);
    k_i2h<<<dim3(6, 6, 120), 128>>>(inputs, i2h_w, i2h_b);

    for (int t = 0; t < Tt; t++) {
        k_fconv<<<dim3(6, 6, 8), 128>>>(inputs, t, i2f_w, i2f_b, h2f_w, h2f_b);
        k_flows<<<dim3(6, 6, 8), 128>>>(flows_w, flows_b);
        k_gather<<<(Bq * Lq * HW + 255) / 256, 256>>>();
        k_gemm_mma<<<dim3(HW / 128, Bq), 256, G_SMEM_BYTES>>>(wrap_w, wrap_b, out, t);
    }

    long long outputs_elems = (long long)Bq * Tt * HID * HW;
    if ((long long)out_size >= outputs_elems + nh) {
        k_hlast<<<(nh + 255) / 256, 256>>>(out + outputs_elems);
    }
}

// round 4
// speedup vs baseline: 1.8653x; 1.3123x over previous
#include <cuda_runtime.h>
#include <math.h>
#include <stdint.h>

// ---- problem constants ----
#define Bq   4
#define Tt   10
#define CINq 8
#define Hh   96
#define Ww   96
#define HW   9216          // 96*96
#define HID  64
#define Lq   13
#define C3   192           // 3*hid
#define KW   832           // L*hid
#define FCH  32

// ---- scratch (device globals; no allocation allowed) ----
__device__ float g_i2h[(size_t)Bq * Tt * C3 * HW];      // 283 MB
__device__ float g_hA[(size_t)Bq * HID * HW];           // ping
__device__ float g_hB[(size_t)Bq * HID * HW];           // pong
__device__ float g_f[(size_t)Bq * FCH * HW];
__device__ float g_flows[(size_t)Bq * 2 * Lq * HW];
__device__ uint32_t g_Bh[(size_t)C3 * KW];              // wrap_w tf32 hi
__device__ uint32_t g_Bl[(size_t)C3 * KW];              // wrap_w tf32 lo

// ---- helpers ----
typedef unsigned long long u64;
__device__ __forceinline__ u64 pack2(float x, float y) {
    u64 r; asm("mov.b64 %0, {%1,%2};" : "=l"(r) : "f"(x), "f"(y)); return r;
}
__device__ __forceinline__ void unpack2(u64 v, float& x, float& y) {
    asm("mov.b64 {%0,%1}, %2;" : "=f"(x), "=f"(y) : "l"(v));
}
__device__ __forceinline__ void fma2(u64& d, u64 a, u64 b) {
    asm("fma.rn.f32x2 %0, %1, %2, %0;" : "+l"(d) : "l"(a), "l"(b));
}
__device__ __forceinline__ uint32_t tf32r(float x) {
    uint32_t r; asm("cvt.rna.tf32.f32 %0, %1;" : "=r"(r) : "f"(x)); return r;
}

// ---------------------------------------------------------------------------
__global__ void k_init_h(const float* __restrict__ state) {
    int i = blockIdx.x * 256 + threadIdx.x;
    if (i < Bq * HID * HW) g_hA[i] = state[i];
}
__global__ void k_hlast(float* __restrict__ dst) {
    int i = blockIdx.x * 256 + threadIdx.x;
    if (i < Bq * HID * HW) dst[i] = g_hA[i];
}
__global__ void k_prep_b(const float* __restrict__ wrap_w) {
    int i = blockIdx.x * 256 + threadIdx.x;
    if (i < C3 * KW) {
        float v = wrap_w[i];
        uint32_t h = tf32r(v);
        g_Bh[i] = h;
        g_Bl[i] = tf32r(v - __uint_as_float(h));
    }
}

// ---------------------------------------------------------------------------
// i2h: conv3x3 pad1, (40,8,96,96) -> (40,192,96,96). Runs once. f32x2 packed.
__global__ __launch_bounds__(128)
void k_i2h(const float* __restrict__ x, const float* __restrict__ w,
           const float* __restrict__ bias) {
    __shared__ float s_in[CINq * 18 * 18];
    __shared__ float s_w[72 * 32];           // [kidx][co] co-contiguous
    const int n    = blockIdx.z % 40;
    const int half = blockIdx.z / 40;
    const int y0 = blockIdx.y * 16, x0 = blockIdx.x * 16;
    const int tid = threadIdx.x;
    const int tx = tid & 15, ty = tid >> 4;

    const float* xin = x + (size_t)n * CINq * HW;
    for (int idx = tid; idx < CINq * 18 * 18; idx += 128) {
        int ci = idx / 324, r = (idx / 18) % 18, c = idx % 18;
        int gy = y0 - 1 + r, gx = x0 - 1 + c;
        float v = 0.f;
        if (gy >= 0 && gy < Hh && gx >= 0 && gx < Ww) v = xin[ci * HW + gy * Ww + gx];
        s_in[idx] = v;
    }
    for (int cob = half * 64; cob < half * 64 + 64; cob += 32) {
        __syncthreads();
        for (int idx = tid; idx < 72 * 32; idx += 128) {
            int kk = idx >> 5, co = idx & 31;
            s_w[idx] = w[(cob + co) * 72 + kk];
        }
        __syncthreads();
        u64 accA[16], accB[16];
#pragma unroll
        for (int q = 0; q < 16; q++) {
            u64 v = pack2(bias[cob + 2 * q], bias[cob + 2 * q + 1]);
            accA[q] = v; accB[q] = v;
        }
        for (int ci = 0; ci < CINq; ci++) {
#pragma unroll
            for (int ky = 0; ky < 3; ky++) {
                const float* r0 = &s_in[ci * 324 + (ty + ky) * 18 + tx];
                const float* r1 = &s_in[ci * 324 + (ty + 8 + ky) * 18 + tx];
#pragma unroll
                for (int kx = 0; kx < 3; kx++) {
                    u64 a0 = pack2(r0[kx], r0[kx]);
                    u64 a1 = pack2(r1[kx], r1[kx]);
                    const u64* wp = (const u64*)&s_w[(ci * 9 + ky * 3 + kx) * 32];
#pragma unroll
                    for (int q = 0; q < 16; q++) {
                        u64 w2 = wp[q];
                        fma2(accA[q], a0, w2);
                        fma2(accB[q], a1, w2);
                    }
                }
            }
        }
        float* outp = g_i2h + (size_t)n * C3 * HW + (size_t)cob * HW + (y0 + ty) * Ww + (x0 + tx);
#pragma unroll
        for (int q = 0; q < 16; q++) {
            float v0, v1, v2, v3;
            unpack2(accA[q], v0, v1);
            unpack2(accB[q], v2, v3);
            outp[(size_t)(2 * q) * HW] = v0;
            outp[(size_t)(2 * q + 1) * HW] = v1;
            outp[(size_t)(2 * q) * HW + 8 * Ww] = v2;
            outp[(size_t)(2 * q + 1) * HW + 8 * Ww] = v3;
        }
    }
}

// ---------------------------------------------------------------------------
// f = tanh(conv5x5(x_t, i2f) + conv5x5(h, h2f)). f32x2 packed, 16co groups.
__global__ __launch_bounds__(128)
void k_fconv(const float* __restrict__ xall, int t, int swap,
             const float* __restrict__ wi, const float* __restrict__ bi,
             const float* __restrict__ wh, const float* __restrict__ bh) {
    __shared__ float s_in[8 * 400];
    __shared__ float s_w[200 * 16];          // [kidx][co]
    const int b   = blockIdx.z & 3;
    const int grp = blockIdx.z >> 2;
    const int co0 = grp * 16;
    const int y0 = blockIdx.y * 16, x0 = blockIdx.x * 16;
    const int tid = threadIdx.x;
    const int tx = tid & 15, ty = tid >> 4;
    const float* hsrc = swap ? g_hB : g_hA;

    u64 accA[8], accB[8];
#pragma unroll
    for (int q = 0; q < 8; q++) {
        u64 v = pack2(bi[co0 + 2 * q] + bh[co0 + 2 * q],
                      bi[co0 + 2 * q + 1] + bh[co0 + 2 * q + 1]);
        accA[q] = v; accB[q] = v;
    }

    for (int chunk = 0; chunk < 9; chunk++) {
        const float* src = (chunk == 0)
            ? xall + (size_t)(b * Tt + t) * CINq * HW
            : hsrc + (size_t)b * HID * HW + (size_t)(chunk - 1) * 8 * HW;
        __syncthreads();
        for (int idx = tid; idx < 8 * 400; idx += 128) {
            int ci = idx / 400, r = (idx / 20) % 20, c = idx % 20;
            int gy = y0 - 2 + r, gx = x0 - 2 + c;
            float v = 0.f;
            if (gy >= 0 && gy < Hh && gx >= 0 && gx < Ww) v = src[ci * HW + gy * Ww + gx];
            s_in[idx] = v;
        }
        if (chunk == 0) {
            for (int idx = tid; idx < 200 * 16; idx += 128) {
                int kk = idx >> 4, co = idx & 15;
                s_w[idx] = wi[(co0 + co) * 200 + kk];
            }
        } else {
            int cioff = (chunk - 1) * 8;
            for (int idx = tid; idx < 200 * 16; idx += 128) {
                int kk = idx >> 4, co = idx & 15;
                int ci = kk / 25, k25 = kk % 25;
                s_w[idx] = wh[((co0 + co) * 64 + cioff + ci) * 25 + k25];
            }
        }
        __syncthreads();
        for (int ci = 0; ci < 8; ci++) {
#pragma unroll
            for (int ky = 0; ky < 5; ky++) {
                const float* r0 = &s_in[ci * 400 + (ty + ky) * 20 + tx];
                const float* r1 = &s_in[ci * 400 + (ty + 8 + ky) * 20 + tx];
#pragma unroll
                for (int kx = 0; kx < 5; kx++) {
                    u64 a0 = pack2(r0[kx], r0[kx]);
                    u64 a1 = pack2(r1[kx], r1[kx]);
                    const u64* wp = (const u64*)&s_w[(ci * 25 + ky * 5 + kx) * 16];
#pragma unroll
                    for (int q = 0; q < 8; q++) {
                        u64 w2 = wp[q];
                        fma2(accA[q], a0, w2);
                        fma2(accB[q], a1, w2);
                    }
                }
            }
        }
    }
    float* outp = g_f + (size_t)b * FCH * HW + (size_t)co0 * HW + (y0 + ty) * Ww + (x0 + tx);
#pragma unroll
    for (int q = 0; q < 8; q++) {
        float v0, v1, v2, v3;
        unpack2(accA[q], v0, v1);
        unpack2(accB[q], v2, v3);
        outp[(size_t)(2 * q) * HW] = tanhf(v0);
        outp[(size_t)(2 * q + 1) * HW] = tanhf(v1);
        outp[(size_t)(2 * q) * HW + 8 * Ww] = tanhf(v2);
        outp[(size_t)(2 * q + 1) * HW + 8 * Ww] = tanhf(v3);
    }
}

// ---------------------------------------------------------------------------
// flows = conv5x5(f, flows_w) : (4,26,96,96). 2 groups of 13 co, f32x2 packed.
__global__ __launch_bounds__(128)
void k_flows(const float* __restrict__ w, const float* __restrict__ bias) {
    __shared__ float s_in[8 * 400];
    __shared__ float s_w[200 * 14];          // [kidx][co], co 13 zero-padded to 14
    const int b   = blockIdx.z & 3;
    const int grp = blockIdx.z >> 2;
    const int co0 = grp * 13;
    const int y0 = blockIdx.y * 16, x0 = blockIdx.x * 16;
    const int tid = threadIdx.x;
    const int tx = tid & 15, ty = tid >> 4;

    u64 accA[7], accB[7];
#pragma unroll
    for (int q = 0; q < 7; q++) {
        float b0 = bias[co0 + 2 * q];
        float b1 = (2 * q + 1 < 13) ? bias[co0 + 2 * q + 1] : 0.f;
        u64 v = pack2(b0, b1);
        accA[q] = v; accB[q] = v;
    }

    for (int chunk = 0; chunk < 4; chunk++) {
        const float* src = g_f + (size_t)b * FCH * HW + (size_t)chunk * 8 * HW;
        __syncthreads();
        for (int idx = tid; idx < 8 * 400; idx += 128) {
            int ci = idx / 400, r = (idx / 20) % 20, c = idx % 20;
            int gy = y0 - 2 + r, gx = x0 - 2 + c;
            float v = 0.f;
            if (gy >= 0 && gy < Hh && gx >= 0 && gx < Ww) v = src[ci * HW + gy * Ww + gx];
            s_in[idx] = v;
        }
        int cioff = chunk * 8;
        for (int idx = tid; idx < 200 * 14; idx += 128) {
            int kk = idx / 14, co = idx % 14;
            int ci = kk / 25, k25 = kk % 25;
            float v = 0.f;
            if (co < 13) v = w[((co0 + co) * 32 + cioff + ci) * 25 + k25];
            s_w[idx] = v;
        }
        __syncthreads();
        for (int ci = 0; ci < 8; ci++) {
#pragma unroll
            for (int ky = 0; ky < 5; ky++) {
                const float* r0 = &s_in[ci * 400 + (ty + ky) * 20 + tx];
                const float* r1 = &s_in[ci * 400 + (ty + 8 + ky) * 20 + tx];
#pragma unroll
                for (int kx = 0; kx < 5; kx++) {
                    u64 a0 = pack2(r0[kx], r0[kx]);
                    u64 a1 = pack2(r1[kx], r1[kx]);
                    const u64* wp = (const u64*)&s_w[(ci * 25 + ky * 5 + kx) * 14];
#pragma unroll
                    for (int q = 0; q < 7; q++) {
                        u64 w2 = wp[q];
                        fma2(accA[q], a0, w2);
                        fma2(accB[q], a1, w2);
                    }
                }
            }
        }
    }
    float* outp = g_flows + (size_t)b * 2 * Lq * HW + (size_t)co0 * HW + (y0 + ty) * Ww + (x0 + tx);
#pragma unroll
    for (int q = 0; q < 7; q++) {
        float v0, v1, v2, v3;
        unpack2(accA[q], v0, v1);
        unpack2(accB[q], v2, v3);
        outp[(size_t)(2 * q) * HW] = v0;
        outp[(size_t)(2 * q) * HW + 8 * Ww] = v2;
        if (2 * q + 1 < 13) {
            outp[(size_t)(2 * q + 1) * HW] = v1;
            outp[(size_t)(2 * q + 1) * HW + 8 * Ww] = v3;
        }
    }
}

// ---------------------------------------------------------------------------
// h2h GEMM (mma.sync m16n8k8 tf32, 3-term hi/lo) with FUSED grid-sample gather
// in the A-stage and fused GRU gates in the epilogue.
// CTA: 128 px x 192 gates, K=832 in 26 chunks of 32 (chunk = half of one l).
#define AS 36
#define CS 197
#define GW_AHI 0
#define GW_ALO 4608    // 128*36
#define GW_BHI 9216
#define GW_BLO 16128
#define G_SMEM_BYTES (128 * CS * 4 > 23040 * 4 ? 128 * CS * 4 : 23040 * 4)

__device__ __forceinline__ void mma8(float d[4], const uint32_t a[4],
                                     uint32_t b0, uint32_t b1) {
    asm volatile(
        "mma.sync.aligned.m16n8k8.row.col.f32.tf32.tf32.f32 "
        "{%0,%1,%2,%3}, {%4,%5,%6,%7}, {%8,%9}, {%0,%1,%2,%3};"
        : "+f"(d[0]), "+f"(d[1]), "+f"(d[2]), "+f"(d[3])
        : "r"(a[0]), "r"(a[1]), "r"(a[2]), "r"(a[3]), "r"(b0), "r"(b1));
}

__global__ __launch_bounds__(256, 1)
void k_gemm_mma(const float* __restrict__ wrap_b, float* __restrict__ out,
                int t, int swap) {
    extern __shared__ __align__(16) float sm[];
    uint32_t* Ah = (uint32_t*)(sm + GW_AHI);
    uint32_t* Al = (uint32_t*)(sm + GW_ALO);
    uint32_t* Bh = (uint32_t*)(sm + GW_BHI);
    uint32_t* Bl = (uint32_t*)(sm + GW_BLO);

    const int tid = threadIdx.x;
    const int wid = tid >> 5, lane = tid & 31;
    const int g = lane >> 2, tg = lane & 3;
    const int b  = blockIdx.y;
    const int p0 = blockIdx.x * 128;
    const int wm = (wid >> 2) * 64;
    const int wn = (wid & 3) * 48;

    const float* h_r = swap ? g_hB : g_hA;
    float*       h_w = swap ? g_hA : g_hB;

    // gather-thread mapping: pixel + channel-half
    const int pl = tid & 127, ch2 = tid >> 7;
    const int p = p0 + pl;
    const int py = p / Ww, px = p - py * Ww;
    const float* Fb = g_flows + (size_t)b * 2 * Lq * HW;
    const float* hbase = h_r + (size_t)b * HID * HW;

    float acc[4][6][4];
#pragma unroll
    for (int mt = 0; mt < 4; mt++)
#pragma unroll
        for (int nt = 0; nt < 6; nt++)
#pragma unroll
            for (int q = 0; q < 4; q++) acc[mt][nt][q] = 0.f;

    for (int c = 0; c < 26; c++) {
        const int k0 = c * 32;
        __syncthreads();
        // ---- A stage: fused bilinear gather, convert to tf32 hi/lo ----
        {
            const int l = k0 >> 6;
            float fx = Fb[(size_t)(2 * l) * HW + p];
            float fy = Fb[(size_t)(2 * l + 1) * HW + p];
            float ix = (float)px - fx - 0.5f;
            float iy = (float)py - fy - 0.5f;
            float ix0f = floorf(ix), iy0f = floorf(iy);
            float wx1 = ix - ix0f, wy1 = iy - iy0f;
            float wx0 = 1.f - wx1, wy0 = 1.f - wy1;
            int ix0 = (int)ix0f, iy0 = (int)iy0f;
            int ix1 = ix0 + 1, iy1 = iy0 + 1;
            bool vx0 = (ix0 >= 0 && ix0 < Ww), vx1 = (ix1 >= 0 && ix1 < Ww);
            bool vy0 = (iy0 >= 0 && iy0 < Hh), vy1 = (iy1 >= 0 && iy1 < Hh);
            float w00 = (vy0 && vx0) ? wy0 * wx0 : 0.f;
            float w01 = (vy0 && vx1) ? wy0 * wx1 : 0.f;
            float w10 = (vy1 && vx0) ? wy1 * wx0 : 0.f;
            float w11 = (vy1 && vx1) ? wy1 * wx1 : 0.f;
            int xc0 = min(max(ix0, 0), Ww - 1), xc1 = min(max(ix1, 0), Ww - 1);
            int yc0 = min(max(iy0, 0), Hh - 1), yc1 = min(max(iy1, 0), Hh - 1);
            int o00 = yc0 * Ww + xc0, o01 = yc0 * Ww + xc1;
            int o10 = yc1 * Ww + xc0, o11 = yc1 * Ww + xc1;

            const int cbase = (k0 & 32) + ch2 * 16;
            const float* hb = hbase + (size_t)cbase * HW;
            const uint32_t base = pl * AS + ch2 * 16;
#pragma unroll
            for (int jj = 0; jj < 4; jj++) {
                uint4 hi4, lo4;
#pragma unroll
                for (int q = 0; q < 4; q++) {
                    const float* hc = hb + (size_t)(jj * 4 + q) * HW;
                    float v = w00 * hc[o00] + w01 * hc[o01] + w10 * hc[o10] + w11 * hc[o11];
                    uint32_t h = tf32r(v);
                    uint32_t lo = tf32r(v - __uint_as_float(h));
                    ((uint32_t*)&hi4)[q] = h;
                    ((uint32_t*)&lo4)[q] = lo;
                }
                *(uint4*)(Ah + base + jj * 4) = hi4;
                *(uint4*)(Al + base + jj * 4) = lo4;
            }
        }
        // ---- B stage: preconverted tf32 hi/lo from global ----
#pragma unroll
        for (int i = 0; i < 6; i++) {
            int idx = tid + 256 * i;
            int row = idx >> 3, cc = idx & 7;
            uint4 vh = *(const uint4*)(g_Bh + (size_t)row * KW + k0 + cc * 4);
            uint4 vl = *(const uint4*)(g_Bl + (size_t)row * KW + k0 + cc * 4);
            *(uint4*)(Bh + row * AS + cc * 4) = vh;
            *(uint4*)(Bl + row * AS + cc * 4) = vl;
        }
        __syncthreads();

#pragma unroll
        for (int ks = 0; ks < 4; ks++) {
            const int kk = ks * 8;
            uint32_t ahi[4][4], alo[4][4];
#pragma unroll
            for (int mt = 0; mt < 4; mt++) {
                int base = (wm + mt * 16 + g) * AS + kk + tg;
                ahi[mt][0] = Ah[base];            ahi[mt][2] = Ah[base + 4];
                ahi[mt][1] = Ah[base + 8 * AS];   ahi[mt][3] = Ah[base + 8 * AS + 4];
                alo[mt][0] = Al[base];            alo[mt][2] = Al[base + 4];
                alo[mt][1] = Al[base + 8 * AS];   alo[mt][3] = Al[base + 8 * AS + 4];
            }
#pragma unroll
            for (int nt = 0; nt < 6; nt++) {
                int rb = (wn + nt * 8 + g) * AS + kk + tg;
                uint32_t bh0 = Bh[rb], bh1 = Bh[rb + 4];
                uint32_t bl0 = Bl[rb], bl1 = Bl[rb + 4];
#pragma unroll
                for (int mt = 0; mt < 4; mt++) {
                    mma8(acc[mt][nt], ahi[mt], bh0, bh1);
                    mma8(acc[mt][nt], ahi[mt], bl0, bl1);
                    mma8(acc[mt][nt], alo[mt], bh0, bh1);
                }
            }
        }
    }

    // ---- write fragments to SMEM C tile, then fused gates ----
    __syncthreads();
    float* C = sm;
#pragma unroll
    for (int mt = 0; mt < 4; mt++) {
#pragma unroll
        for (int nt = 0; nt < 6; nt++) {
            int row = wm + mt * 16 + g;
            int col = wn + nt * 8 + tg * 2;
            C[row * CS + col]           = acc[mt][nt][0];
            C[row * CS + col + 1]       = acc[mt][nt][1];
            C[(row + 8) * CS + col]     = acc[mt][nt][2];
            C[(row + 8) * CS + col + 1] = acc[mt][nt][3];
        }
    }
    __syncthreads();

    const float* i2hp = g_i2h + (size_t)(b * Tt + t) * C3 * HW;
#pragma unroll 4
    for (int idx = tid; idx < 128 * 64; idx += 256) {
        int ppl = idx & 127, cc = idx >> 7;
        int pp = p0 + ppl;
        float rh = C[ppl * CS + cc]       + __ldg(&wrap_b[cc]);
        float uh = C[ppl * CS + cc + 64]  + __ldg(&wrap_b[cc + 64]);
        float nh = C[ppl * CS + cc + 128] + __ldg(&wrap_b[cc + 128]);
        float r = 1.f / (1.f + expf(-(i2hp[(size_t)cc * HW + pp] + rh)));
        float u = 1.f / (1.f + expf(-(i2hp[(size_t)(cc + 64) * HW + pp] + uh)));
        float n = 1.f / (1.f + expf(-(i2hp[(size_t)(cc + 128) * HW + pp] + r * nh)));
        size_t hidx = ((size_t)b * HID + cc) * HW + pp;
        float hp = h_r[hidx];
        float hn = (1.f - u) * n + u * hp;
        h_w[hidx] = hn;
        out[((size_t)(b * Tt + t) * HID + cc) * HW + pp] = hn;
    }
}

// ---------------------------------------------------------------------------
extern "C" void kernel_launch(void* const* d_in, const int* in_sizes, int n_in,
                              void* d_out, int out_size) {
    const float* inputs  = (const float*)d_in[0];
    const float* state   = (const float*)d_in[1];
    const float* i2h_w   = (const float*)d_in[2];
    const float* i2h_b   = (const float*)d_in[3];
    const float* i2f_w   = (const float*)d_in[4];
    const float* i2f_b   = (const float*)d_in[5];
    const float* h2f_w   = (const float*)d_in[6];
    const float* h2f_b   = (const float*)d_in[7];
    const float* flows_w = (const float*)d_in[8];
    const float* flows_b = (const float*)d_in[9];
    const float* wrap_w  = (const float*)d_in[10];
    const float* wrap_b  = (const float*)d_in[11];
    float* out = (float*)d_out;

    cudaFuncSetAttribute(k_gemm_mma, cudaFuncAttributeMaxDynamicSharedMemorySize,
                         G_SMEM_BYTES);

    const int nh = Bq * HID * HW;
    k_init_h<<<(nh + 255) / 256, 256>>>(state);
    k_prep_b<<<(C3 * KW + 255) / 256, 256>>>(wrap_w);
    k_i2h<<<dim3(6, 6, 120), 128>>>(inputs, i2h_w, i2h_b);

    for (int t = 0; t < Tt; t++) {
        int swap = t & 1;
        k_fconv<<<dim3(6, 6, 8), 128>>>(inputs, t, swap, i2f_w, i2f_b, h2f_w, h2f_b);
        k_flows<<<dim3(6, 6, 8), 128>>>(flows_w, flows_b);
        k_gemm_mma<<<dim3(HW / 128, Bq), 256, G_SMEM_BYTES>>>(wrap_b, out, t, swap);
    }

    long long outputs_elems = (long long)Bq * Tt * HID * HW;
    if ((long long)out_size >= outputs_elems + nh) {
        k_hlast<<<(nh + 255) / 256, 256>>>(out + outputs_elems);
    }
}